// round 1
// baseline (speedup 1.0000x reference)
#include <cuda_runtime.h>

#define S 2048
#define B 64
#define H 8
#define KK 12
#define NPOS 11
#define TBL 4096  // 1<<KK

// Scratch (no allocations allowed): __device__ globals.
__device__ unsigned long long g_tokmask[S];
__device__ uint4 g_AQ4[S];              // 8 x u16 per s: (h<<12) + addr_q
__device__ uint4 g_AK4[S];              // 8 x u16 per s: addr_k
__device__ uint4 g_AP4[S];              // 8 x u16 per rel: addr_p
__device__ uint4 g_tb4[H * TBL / 16];   // head_table as bytes, [h][addr]
__device__ float g_values[S * B];       // values[s][b] = table_v[b][addr_v(s,b)]

// ---------------------------------------------------------------------------
// Prep 1: pack each token row (64 x int 0/1) into a 64-bit mask. One warp per s.
__global__ void k_tokmask(const int* __restrict__ tokens) {
    int gw = (blockIdx.x * blockDim.x + threadIdx.x) >> 5;
    int lane = threadIdx.x & 31;
    if (gw >= S) return;
    int t0 = tokens[gw * B + lane];
    int t1 = tokens[gw * B + 32 + lane];
    unsigned lo = __ballot_sync(0xffffffffu, t0 != 0);
    unsigned hi = __ballot_sync(0xffffffffu, t1 != 0);
    if (lane == 0)
        g_tokmask[gw] = (unsigned long long)lo | ((unsigned long long)hi << 32);
}

// ---------------------------------------------------------------------------
// Prep 2: byte table + per-(s,h) partial addresses (disjoint bit groups).
__global__ void k_tables(const int* __restrict__ conn_heads,
                         const float* __restrict__ head_table) {
    int i = blockIdx.x * blockDim.x + threadIdx.x;
    if (i < H * TBL) {
        ((unsigned char*)g_tb4)[i] = (head_table[i] != 0.0f) ? 1 : 0;
    }
    if (i < S * H) {
        int s = i >> 3, h = i & 7;
        unsigned long long tm = g_tokmask[s];
        int aq = 0, ak = 0, ap = 0;
#pragma unroll
        for (int j = 0; j < KK; j++) {
            int c = __ldg(&conn_heads[h * KK + j]);
            int p2 = 1 << (KK - 1 - j);
            if (c < B)          aq += (int)((tm >> c) & 1) * p2;
            else if (c < 2 * B) ak += (int)((tm >> (c - B)) & 1) * p2;
            else                ap += ((s >> (NPOS - 1 - (c - 2 * B))) & 1) * p2;
        }
        ((unsigned short*)g_AQ4)[i] = (unsigned short)((h << 12) + aq);
        ((unsigned short*)g_AK4)[i] = (unsigned short)ak;
        ((unsigned short*)g_AP4)[i] = (unsigned short)ap;
    }
}

// ---------------------------------------------------------------------------
// Prep 3: values[s][b] = table_v[b][addr_v(s,b)]
__global__ void k_values(const int* __restrict__ conn_v,
                         const float* __restrict__ table_v) {
    int i = blockIdx.x * blockDim.x + threadIdx.x;
    if (i >= S * B) return;
    int s = i >> 6, b = i & 63;
    unsigned long long tm = g_tokmask[s];
    int addr = 0;
#pragma unroll
    for (int j = 0; j < KK; j++) {
        int c = __ldg(&conn_v[b * KK + j]);
        addr += (int)((tm >> c) & 1) << (KK - 1 - j);
    }
    g_values[i] = __ldg(&table_v[b * TBL + addr]);
}

// ---------------------------------------------------------------------------
// Main: one block per query row q. Scan keys k in ascending 256-wide chunks,
// early-exit when any vote hits the maximum (H=8). Argmax with first-index
// tie-break via encoded key (v<<11)|(2047-k). Writes the output row directly.
__global__ void __launch_bounds__(256) k_main(float* __restrict__ out) {
    __shared__ unsigned char s_tb[H * TBL];   // 32 KB byte table
    __shared__ int s_red[8];
    __shared__ int s_flag;
    __shared__ int s_best;

    int tid = threadIdx.x;
    int q = blockIdx.x;

    // Stage table into shared (2048 uint4, 8 per thread).
    uint4* st4 = (uint4*)s_tb;
#pragma unroll
    for (int i = 0; i < 8; i++) st4[tid + i * 256] = g_tb4[tid + i * 256];
    if (tid == 0) s_flag = 0;
    uint4 aq = g_AQ4[q];
    __syncthreads();

    int best = -1;
    for (int c0 = 0; c0 <= q; c0 += 256) {
        int k = c0 + tid;
        int v = 0;
        if (k <= q) {
            uint4 ak = __ldg(&g_AK4[k]);
            uint4 ap = __ldg(&g_AP4[q - k]);
            // packed u16 adds: (h<<12)+aq+ak+ap <= 40957 per lane, no carry.
            unsigned wx = ak.x + ap.x + aq.x;
            unsigned wy = ak.y + ap.y + aq.y;
            unsigned wz = ak.z + ap.z + aq.z;
            unsigned ww = ak.w + ap.w + aq.w;
            v = s_tb[wx & 0xFFFF] + s_tb[wx >> 16]
              + s_tb[wy & 0xFFFF] + s_tb[wy >> 16]
              + s_tb[wz & 0xFFFF] + s_tb[wz >> 16]
              + s_tb[ww & 0xFFFF] + s_tb[ww >> 16];
            int enc = (v << 11) | (2047 - k);
            best = max(best, enc);
        }
        // Block-wide early exit: vote == H is the global maximum; scanning
        // ascending, the first chunk containing it holds the answer.
        unsigned b8 = __ballot_sync(0xffffffffu, v == H);
        if ((tid & 31) == 0 && b8) s_flag = 1;
        __syncthreads();
        int stop = s_flag;
        __syncthreads();   // protect s_flag read from next-iteration writes
        if (stop) break;
    }

    // Block max-reduce of encoded best.
#pragma unroll
    for (int off = 16; off; off >>= 1)
        best = max(best, __shfl_xor_sync(0xffffffffu, best, off));
    if ((tid & 31) == 0) s_red[tid >> 5] = best;
    __syncthreads();
    if (tid == 0) {
        int m = s_red[0];
#pragma unroll
        for (int i = 1; i < 8; i++) m = max(m, s_red[i]);
        s_best = m;
    }
    __syncthreads();

    if (tid < B) {
        int m = s_best;
        int bv = m >> 11;
        int bk = 2047 - (m & 2047);
        out[q * B + tid] = (bv > 0) ? g_values[bk * B + tid] : 0.0f;
    }
}

// ---------------------------------------------------------------------------
extern "C" void kernel_launch(void* const* d_in, const int* in_sizes, int n_in,
                              void* d_out, int out_size) {
    const int*   tokens     = (const int*)d_in[0];
    const int*   conn_heads = (const int*)d_in[1];
    const float* head_table = (const float*)d_in[2];
    const int*   conn_v     = (const int*)d_in[3];
    const float* table_v    = (const float*)d_in[4];
    float* out = (float*)d_out;

    k_tokmask<<<(S * 32) / 256, 256>>>(tokens);
    k_tables<<<(H * TBL + 255) / 256, 256>>>(conn_heads, head_table);
    k_values<<<(S * B + 255) / 256, 256>>>(conn_v, table_v);
    k_main<<<S, 256>>>(out);
}